// round 2
// baseline (speedup 1.0000x reference)
#include <cuda_runtime.h>
#include <cstdint>

// Problem constants
#define Bx 8
#define Cc 128
#define Hh 128
#define Ww 128
#define KWIN 9
#define PWPAD 4
#define Tt 128   // conv (row) dimension
#define Ss 128   // scan dimension

// smem layout constants
#define CP 129                                   // s_prev pitch (floats): conflict-free column access
#define WPITCH 10                                // s_wt per-(k,ci) pitch: conflict-free LDS.64
#define SPREV_FLOATS ((Tt + 2*PWPAD) * CP)       // 136*129 = 17544
#define SWT_FLOATS (KWIN * Cc * WPITCH)          // 11520
#define SMEM_BYTES ((SPREV_FLOATS + SWT_FLOATS) * 4)  // 116256 bytes
#define REDP 65                                  // reduction pitch

// Scratch: 2 x 64MB fp32 tensors in (B, S, T, C) layout (static __device__, allowed)
__device__ float g_buf0[(size_t)Bx*Ss*Tt*Cc];
__device__ float g_buf1[(size_t)Bx*Ss*Tt*Cc];

// ---------------------------------------------------------------------------
// transpose_in: x (B,C,H,W) -> buf (B,H,W,C)
// grid (W/32, C/32, B*H), block (32,8)
__global__ void transpose_in_kernel(const float* __restrict__ x, float* __restrict__ out) {
    __shared__ float tile[32][33];
    int w0 = blockIdx.x * 32, c0 = blockIdx.y * 32;
    int bh = blockIdx.z;
    int b = bh >> 7, h = bh & 127;
#pragma unroll
    for (int j = 0; j < 32; j += 8) {
        int c = c0 + threadIdx.y + j;
        tile[threadIdx.y + j][threadIdx.x] =
            x[((size_t)(b * Cc + c) * Hh + h) * Ww + w0 + threadIdx.x];
    }
    __syncthreads();
#pragma unroll
    for (int j = 0; j < 32; j += 8) {
        int w = w0 + threadIdx.y + j;
        out[((size_t)(b * Hh + h) * Ww + w) * Cc + c0 + threadIdx.x] =
            tile[threadIdx.x][threadIdx.y + j];
    }
}

// transpose_mid: (B,S,T,C) -> (B,T,S,C)  (swap dims 1,2; C stays contiguous)
// grid = B*S blocks, 128 threads
__global__ void transpose_mid_kernel(const float* __restrict__ in, float* __restrict__ out) {
    int bs = blockIdx.x;
    int b = bs >> 7, s = bs & 127;
    int tid = threadIdx.x;
    int toff = tid >> 5;          // 4 t's per pass
    int c4 = (tid & 31) * 4;
    for (int tb = 0; tb < Tt; tb += 4) {
        int t = tb + toff;
        float4 v = *(const float4*)(in + ((size_t)((b * Ss + s) * Tt + t)) * Cc + c4);
        *(float4*)(out + ((size_t)((b * Tt + t) * Ss + s)) * Cc + c4) = v;
    }
}

// transpose_out: buf1 (B, W, H, C) -> out (B, C, H, W)
// grid (W/32, C/32, B*H), block (32,8)
__global__ void transpose_out_kernel(const float* __restrict__ in, float* __restrict__ out) {
    __shared__ float tile[32][33];
    int w0 = blockIdx.x * 32, c0 = blockIdx.y * 32;
    int bh = blockIdx.z;
    int b = bh >> 7, h = bh & 127;
#pragma unroll
    for (int j = 0; j < 32; j += 8) {
        int w = w0 + threadIdx.y + j;
        tile[threadIdx.y + j][threadIdx.x] =
            in[((size_t)(b * Ww + w) * Hh + h) * Cc + c0 + threadIdx.x];
    }
    __syncthreads();
#pragma unroll
    for (int j = 0; j < 32; j += 8) {
        int c = c0 + threadIdx.y + j;
        out[((size_t)(b * Cc + c) * Hh + h) * Ww + w0 + threadIdx.x] =
            tile[threadIdx.x][threadIdx.y + j];
    }
}

// ---------------------------------------------------------------------------
// One scan step: row 'cur' of batch b gets  buf[cur] = buf[cur] + relu(conv(buf[prev]))
// Block = (co-tile of 8 out-channels) x batch. 128 threads:
//   tg = tid>>3 (16 t-groups of 8 t), cg = tid&7 (8-way split of ci, interleaved ci = cg+8i)
// Inner math uses fp32x2 packed FMA (FFMA2) pairing over out-channel pairs:
//   b-operand = LDS.64 weight pair (contiguous), a-operand = dup-packed activation.
__global__ void __launch_bounds__(128, 1) step_kernel(
    const float* __restrict__ Kw, float* __restrict__ buf, int cur, int prev)
{
    extern __shared__ float sm[];
    float* s_prev = sm;                     // [136][CP]
    float* s_wt   = sm + SPREV_FLOATS;      // [KWIN][Cc][WPITCH]
    float* s_red  = s_wt;                   // aliased after compute

    const int tid = threadIdx.x;
    const int b   = blockIdx.y;
    const int co0 = blockIdx.x * 8;

    const float* prow = buf + (size_t)(b * Ss + prev) * Tt * Cc;
    float*       crow = buf + (size_t)(b * Ss + cur) * Tt * Cc;

    // zero pad rows (t = -4..-1 and 128..131)
    for (int idx = tid; idx < PWPAD * Cc; idx += 128) {
        int r = idx >> 7, c = idx & 127;
        s_prev[r * CP + c] = 0.f;
        s_prev[(Tt + PWPAD + r) * CP + c] = 0.f;
    }
    // main rows: coalesced float4 gmem loads, scalar STS (pitch 129)
    for (int idx = tid; idx < Tt * Cc / 4; idx += 128) {
        int t = idx >> 5;
        int c4 = (idx & 31) * 4;
        float4 v = *(const float4*)(prow + t * Cc + c4);
        float* d = &s_prev[(t + PWPAD) * CP + c4];
        d[0] = v.x; d[1] = v.y; d[2] = v.z; d[3] = v.w;
    }
    // weights for this co-tile: s_wt[(k*Cc+ci)*WPITCH + c] = Kw[(k*Cc+ci)*Cc + co0 + c]
    for (int idx = tid; idx < KWIN * Cc * 8; idx += 128) {
        int kc = idx >> 3;
        int c = idx & 7;
        s_wt[kc * WPITCH + c] = Kw[(size_t)kc * Cc + co0 + c];
    }
    __syncthreads();

    const int tg = tid >> 3;
    const int cg = tid & 7;
    const int t0 = tg * 8;

    unsigned long long acc[8][4];
#pragma unroll
    for (int j = 0; j < 8; j++)
#pragma unroll
        for (int cp = 0; cp < 4; cp++) acc[j][cp] = 0ull;

    for (int i = 0; i < 16; ++i) {
        const int ci = cg + 8 * i;
        unsigned long long a2[16];
#pragma unroll
        for (int j = 0; j < 16; ++j) {
            unsigned u = __float_as_uint(s_prev[(t0 + j) * CP + ci]);
            asm("mov.b64 %0, {%1, %1};" : "=l"(a2[j]) : "r"(u));
        }
#pragma unroll
        for (int k = 0; k < KWIN; ++k) {
            const float* wr = &s_wt[(k * Cc + ci) * WPITCH];
#pragma unroll
            for (int cp = 0; cp < 4; ++cp) {
                unsigned long long w2 = *(const unsigned long long*)(wr + 2 * cp);
#pragma unroll
                for (int j = 0; j < 8; ++j) {
                    asm("fma.rn.f32x2 %0, %1, %2, %0;"
                        : "+l"(acc[j][cp]) : "l"(a2[j + k]), "l"(w2));
                }
            }
        }
    }
    __syncthreads();  // done reading s_wt; safe to alias as s_red

    // stash partials: s_red[tid][j*8 + co]
#pragma unroll
    for (int j = 0; j < 8; ++j) {
#pragma unroll
        for (int cp = 0; cp < 4; ++cp) {
            unsigned lo, hi;
            asm("mov.b64 {%0, %1}, %2;" : "=r"(lo), "=r"(hi) : "l"(acc[j][cp]));
            s_red[tid * REDP + j * 8 + 2 * cp]     = __uint_as_float(lo);
            s_red[tid * REDP + j * 8 + 2 * cp + 1] = __uint_as_float(hi);
        }
    }
    __syncthreads();

    // final 8-way reduce: thread (tg, co=cg) owns 8 t's of channel co0+cg
#pragma unroll
    for (int j = 0; j < 8; ++j) {
        float s = 0.f;
#pragma unroll
        for (int g = 0; g < 8; ++g)
            s += s_red[(tg * 8 + g) * REDP + j * 8 + cg];
        int t = t0 + j;
        float xv = crow[t * Cc + co0 + cg];
        crow[t * Cc + co0 + cg] = xv + fmaxf(s, 0.f);
    }
}

// ---------------------------------------------------------------------------
extern "C" void kernel_launch(void* const* d_in, const int* in_sizes, int n_in,
                              void* d_out, int out_size) {
    const float* x    = (const float*)d_in[0];
    const float* k_td = (const float*)d_in[1];
    const float* k_dt = (const float*)d_in[2];
    const float* k_lr = (const float*)d_in[3];
    const float* k_rl = (const float*)d_in[4];
    float* out = (float*)d_out;

    float *b0, *b1;
    cudaGetSymbolAddress((void**)&b0, g_buf0);
    cudaGetSymbolAddress((void**)&b1, g_buf1);

    cudaFuncSetAttribute(step_kernel, cudaFuncAttributeMaxDynamicSharedMemorySize, SMEM_BYTES);

    dim3 tgrid(Ww / 32, Cc / 32, Bx * Hh);
    dim3 tblk(32, 8);
    dim3 sgrid(16, Bx);

    // (B,C,H,W) -> (B,H,W,C)
    transpose_in_kernel<<<tgrid, tblk>>>(x, b0);

    // top-down scan along H (conv over W)
    for (int h = 1; h < Ss; ++h)
        step_kernel<<<sgrid, 128, SMEM_BYTES>>>(k_td, b0, h, h - 1);
    // down-top scan
    for (int h = Ss - 2; h >= 0; --h)
        step_kernel<<<sgrid, 128, SMEM_BYTES>>>(k_dt, b0, h, h + 1);

    // (B,H,W,C) -> (B,W,H,C)
    transpose_mid_kernel<<<Bx * Ss, 128>>>(b0, b1);

    // left-right scan along W (conv over H)
    for (int w = 1; w < Ss; ++w)
        step_kernel<<<sgrid, 128, SMEM_BYTES>>>(k_lr, b1, w, w - 1);
    // right-left scan
    for (int w = Ss - 2; w >= 0; --w)
        step_kernel<<<sgrid, 128, SMEM_BYTES>>>(k_rl, b1, w, w + 1);

    // (B,W,H,C) -> (B,C,H,W)
    transpose_out_kernel<<<tgrid, tblk>>>(b1, out);
}

// round 3
// speedup vs baseline: 1.5433x; 1.5433x over previous
#include <cuda_runtime.h>
#include <cstdint>

// Problem constants
#define Bx 8
#define Cc 128
#define Hh 128
#define Ww 128
#define KWIN 9
#define PWPAD 4
#define Tt 128   // conv (row) dimension
#define Ss 128   // scan dimension

// Block decomposition: 128 blocks = 8 batches x (2 T-halves x 8 co-tiles of 16)
#define THALF 64
#define WIN_ROWS (THALF + 2*PWPAD)      // 72

// smem layout
#define CP 130                           // s_prev pitch: conflict-free for 2tg x 16cg warps
#define WPITCH 18                        // s_wt per-(k,ci) pitch (16 co + 2 pad), conflict-free LDS.64
#define SWT_FLOATS (KWIN * Cc * WPITCH)  // 20736
#define REDP 67                          // reduction pitch (3 mod 32 -> conflict-free writes)
#define COPSTRIDE (128 * REDP + 16)      // 8592 (+16 separates cop banks on reduce reads)
#define SRED_FLOATS (2 * COPSTRIDE)      // 17184
#define SPREV_FLOATS (WIN_ROWS * CP)     // 9360
#define REGION_FLOATS SRED_FLOATS        // max(s_prev, s_red) region, aliased
#define SMEM_BYTES ((REGION_FLOATS + SWT_FLOATS) * 4)   // 151680 B

// Scratch tensors (B, S, T, C)
__device__ float g_buf0[(size_t)Bx*Ss*Tt*Cc];
__device__ float g_buf1[(size_t)Bx*Ss*Tt*Cc];
// Per-batch sync counters (one set per scan kernel)
__device__ int g_cnt0[Bx];
__device__ int g_cnt1[Bx];

// ---------------------------------------------------------------------------
__global__ void reset_kernel(int* c0, int* c1) {
    if (threadIdx.x < Bx) { c0[threadIdx.x] = 0; c1[threadIdx.x] = 0; }
}

// transpose_in: x (B,C,H,W) -> buf (B,H,W,C)
__global__ void transpose_in_kernel(const float* __restrict__ x, float* __restrict__ out) {
    __shared__ float tile[32][33];
    int w0 = blockIdx.x * 32, c0 = blockIdx.y * 32;
    int bh = blockIdx.z;
    int b = bh >> 7, h = bh & 127;
#pragma unroll
    for (int j = 0; j < 32; j += 8) {
        int c = c0 + threadIdx.y + j;
        tile[threadIdx.y + j][threadIdx.x] =
            x[((size_t)(b * Cc + c) * Hh + h) * Ww + w0 + threadIdx.x];
    }
    __syncthreads();
#pragma unroll
    for (int j = 0; j < 32; j += 8) {
        int w = w0 + threadIdx.y + j;
        out[((size_t)(b * Hh + h) * Ww + w) * Cc + c0 + threadIdx.x] =
            tile[threadIdx.x][threadIdx.y + j];
    }
}

// transpose_mid: (B,S,T,C) -> (B,T,S,C)
__global__ void transpose_mid_kernel(const float* __restrict__ in, float* __restrict__ out) {
    int bs = blockIdx.x;
    int b = bs >> 7, s = bs & 127;
    int tid = threadIdx.x;
    int toff = tid >> 5;
    int c4 = (tid & 31) * 4;
    for (int tb = 0; tb < Tt; tb += 4) {
        int t = tb + toff;
        float4 v = *(const float4*)(in + ((size_t)((b * Ss + s) * Tt + t)) * Cc + c4);
        *(float4*)(out + ((size_t)((b * Tt + t) * Ss + s)) * Cc + c4) = v;
    }
}

// transpose_out: buf1 (B, W, H, C) -> out (B, C, H, W)
__global__ void transpose_out_kernel(const float* __restrict__ in, float* __restrict__ out) {
    __shared__ float tile[32][33];
    int w0 = blockIdx.x * 32, c0 = blockIdx.y * 32;
    int bh = blockIdx.z;
    int b = bh >> 7, h = bh & 127;
#pragma unroll
    for (int j = 0; j < 32; j += 8) {
        int w = w0 + threadIdx.y + j;
        tile[threadIdx.y + j][threadIdx.x] =
            in[((size_t)(b * Ww + w) * Hh + h) * Cc + c0 + threadIdx.x];
    }
    __syncthreads();
#pragma unroll
    for (int j = 0; j < 32; j += 8) {
        int c = c0 + threadIdx.y + j;
        out[((size_t)(b * Cc + c) * Hh + h) * Ww + w0 + threadIdx.x] =
            tile[threadIdx.x][threadIdx.y + j];
    }
}

// ---------------------------------------------------------------------------
// One scan step for this block's (T-half, 16-co tile):
//   crow[t, co] += relu( sum_{k,ci} prow[t+k-4, ci] * W[k, ci, co] )
__device__ __forceinline__ void scan_step(
    float* __restrict__ s_prev, const float* __restrict__ s_wt, float* __restrict__ s_red,
    const float* __restrict__ prow, float* __restrict__ crow,
    int t0g, int co0, volatile int* vcnt, int* cnt_g, int wait_target, int tid)
{
    // wait for peer blocks of this batch to finish the previous step
    if (tid == 0) {
        while (*vcnt < wait_target) { }
    }
    __syncthreads();

    // fill s_prev window: 72 rows x 128 ch, zero-padded outside [0, Tt)
    // warp covers 4 rows x 8 c4-chunks (2-way STS conflict, coalesced 128B LDG segments)
    for (int idx = tid; idx < WIN_ROWS * 32; idx += 256) {
        int lane = idx & 31;
        int upper = idx >> 5;              // 0..71
        int r_lo = lane >> 3;              // 0..3
        int c_lo = lane & 7;               // 0..7
        int row = r_lo + 4 * (upper >> 2); // 0..71
        int c4 = (c_lo + 8 * (upper & 3)) * 4;
        int tgl = t0g + row - PWPAD;
        float4 v = make_float4(0.f, 0.f, 0.f, 0.f);
        if (tgl >= 0 && tgl < Tt) v = *(const float4*)(prow + tgl * Cc + c4);
        float* d = &s_prev[row * CP + c4];
        d[0] = v.x; d[1] = v.y; d[2] = v.z; d[3] = v.w;
    }
    __syncthreads();

    const int cop = tid >> 7;    // which 8-co half of the 16-co tile
    const int r   = tid & 127;
    const int tg  = r >> 4;      // 8 t-groups of 8 t
    const int cg  = r & 15;      // 16-way ci split

    unsigned long long acc[8][4];
#pragma unroll
    for (int j = 0; j < 8; j++)
#pragma unroll
        for (int cp = 0; cp < 4; cp++) acc[j][cp] = 0ull;

    for (int i = 0; i < 8; ++i) {
        const int ci = cg + 16 * i;
        unsigned long long a2[16];
#pragma unroll
        for (int j = 0; j < 16; ++j) {
            unsigned u = __float_as_uint(s_prev[(tg * 8 + j) * CP + ci]);
            asm("mov.b64 %0, {%1, %1};" : "=l"(a2[j]) : "r"(u));
        }
#pragma unroll
        for (int k = 0; k < KWIN; ++k) {
            const float* wr = &s_wt[(k * Cc + ci) * WPITCH + cop * 8];
#pragma unroll
            for (int cp = 0; cp < 4; ++cp) {
                unsigned long long w2 = *(const unsigned long long*)(wr + 2 * cp);
#pragma unroll
                for (int j = 0; j < 8; ++j) {
                    asm("fma.rn.f32x2 %0, %1, %2, %0;"
                        : "+l"(acc[j][cp]) : "l"(a2[j + k]), "l"(w2));
                }
            }
        }
    }
    __syncthreads();  // done reading s_prev; region now used as s_red

    // stash partials
    float* myred = s_red + cop * COPSTRIDE + r * REDP;
#pragma unroll
    for (int jo = 0; jo < 8; ++jo) {
#pragma unroll
        for (int cp = 0; cp < 4; ++cp) {
            unsigned lo, hi;
            asm("mov.b64 {%0, %1}, %2;" : "=r"(lo), "=r"(hi) : "l"(acc[jo][cp]));
            myred[jo * 8 + 2 * cp]     = __uint_as_float(lo);
            myred[jo * 8 + 2 * cp + 1] = __uint_as_float(hi);
        }
    }
    __syncthreads();

    // 16-way reduce + relu + add x + store
    const int co_loc = tid & 15;
    const int tp     = tid >> 4;        // 0..15
    const int c8     = co_loc & 7;
    const int copp   = co_loc >> 3;
#pragma unroll
    for (int jj = 0; jj < 4; ++jj) {
        int t_loc = tp * 4 + jj;
        int tg2 = t_loc >> 3, jo = t_loc & 7;
        const float* pr = s_red + copp * COPSTRIDE + (tg2 * 16) * REDP + jo * 8 + c8;
        float ssum = 0.f;
#pragma unroll
        for (int g = 0; g < 16; ++g) ssum += pr[g * REDP];
        int t = t0g + t_loc;
        float xv = crow[t * Cc + co0 + co_loc];
        crow[t * Cc + co0 + co_loc] = xv + fmaxf(ssum, 0.f);
    }

    __threadfence();
    __syncthreads();
    if (tid == 0) atomicAdd(cnt_g, 1);
}

// Persistent kernel: forward scan with Kf, then backward scan with Kb (in-place).
__global__ void __launch_bounds__(256, 1) scan_pair_kernel(
    const float* __restrict__ Kf, const float* __restrict__ Kb,
    float* __restrict__ buf, int* cnt)
{
    extern __shared__ float sm[];
    float* s_region = sm;                     // s_prev / s_red alias
    float* s_wt     = sm + REGION_FLOATS;

    const int tid   = threadIdx.x;
    const int blk   = blockIdx.x;
    const int b     = blk >> 4;
    const int slice = blk & 15;
    const int t0g   = (slice & 1) * THALF;
    const int co0   = (slice >> 1) * 16;

    float* bbase = buf + (size_t)b * Ss * Tt * Cc;
    int* cnt_g = cnt + b;
    volatile int* vcnt = cnt + b;

    // load forward weights once
    for (int idx = tid; idx < KWIN * Cc * 16; idx += 256) {
        int kc = idx >> 4, c = idx & 15;
        s_wt[kc * WPITCH + c] = Kf[(size_t)kc * Cc + co0 + c];
    }
    __syncthreads();

    // forward scan: s = 1..127, prev = s-1
    for (int s = 1; s < Ss; ++s) {
        scan_step(s_region, s_wt, s_region,
                  bbase + (size_t)(s - 1) * Tt * Cc,
                  bbase + (size_t)s * Tt * Cc,
                  t0g, co0, vcnt, cnt_g, 16 * (s - 1), tid);
    }

    // switch to backward weights (smem private to block; peers may lag safely)
    __syncthreads();
    for (int idx = tid; idx < KWIN * Cc * 16; idx += 256) {
        int kc = idx >> 4, c = idx & 15;
        s_wt[kc * WPITCH + c] = Kb[(size_t)kc * Cc + co0 + c];
    }
    __syncthreads();

    // backward scan: d = 1..127, cur = 127-d, prev = 128-d
    for (int d = 1; d < Ss; ++d) {
        scan_step(s_region, s_wt, s_region,
                  bbase + (size_t)(Ss - d) * Tt * Cc,
                  bbase + (size_t)(Ss - 1 - d) * Tt * Cc,
                  t0g, co0, vcnt, cnt_g, 16 * (126 + d), tid);
    }
}

// ---------------------------------------------------------------------------
extern "C" void kernel_launch(void* const* d_in, const int* in_sizes, int n_in,
                              void* d_out, int out_size) {
    const float* x    = (const float*)d_in[0];
    const float* k_td = (const float*)d_in[1];
    const float* k_dt = (const float*)d_in[2];
    const float* k_lr = (const float*)d_in[3];
    const float* k_rl = (const float*)d_in[4];
    float* out = (float*)d_out;

    float *b0, *b1;
    int *c0, *c1;
    cudaGetSymbolAddress((void**)&b0, g_buf0);
    cudaGetSymbolAddress((void**)&b1, g_buf1);
    cudaGetSymbolAddress((void**)&c0, g_cnt0);
    cudaGetSymbolAddress((void**)&c1, g_cnt1);

    cudaFuncSetAttribute(scan_pair_kernel, cudaFuncAttributeMaxDynamicSharedMemorySize, SMEM_BYTES);

    dim3 tgrid(Ww / 32, Cc / 32, Bx * Hh);
    dim3 tblk(32, 8);

    reset_kernel<<<1, 32>>>(c0, c1);

    // (B,C,H,W) -> (B,H,W,C)
    transpose_in_kernel<<<tgrid, tblk>>>(x, b0);

    // vertical scans (td then dt), persistent
    scan_pair_kernel<<<128, 256, SMEM_BYTES>>>(k_td, k_dt, b0, c0);

    // (B,H,W,C) -> (B,W,H,C)
    transpose_mid_kernel<<<Bx * Ss, 128>>>(b0, b1);

    // horizontal scans (lr then rl), persistent
    scan_pair_kernel<<<128, 256, SMEM_BYTES>>>(k_lr, k_rl, b1, c1);

    // (B,W,H,C) -> (B,C,H,W)
    transpose_out_kernel<<<tgrid, tblk>>>(b1, out);
}